// round 9
// baseline (speedup 1.0000x reference)
#include <cuda_runtime.h>
#include <cuda_fp16.h>
#include <math.h>
#include <stdint.h>

#define Bn 2
#define Sn 2048
#define Dn 1024
#define Hn 16
#define HDn 64
#define BSn (Bn*Sn)      // 4096
#define N3D (3*Dn)       // 3072
#define NQKV (Bn*Hn*Sn*HDn)

// sub-block (k32): A 128 rows x 128B (16KB) + B 64 rows x 128B (8KB) = 24KB
#define SUB_G  24576
// slot = k64 stage = 2 sub-blocks = 48KB; 2 slots = 96KB -> 2 CTAs/SM
#define SLOT_G (2*SUB_G)
#define SMEM_G (2*SLOT_G)     // 98304
#define SMEM_SC SLOT_G        // scores: single-shot K=64

// ---------------- fp16 hi/lo scratch (device globals) ----------------
__device__ __half s_hs_h[BSn*Dn],  s_hs_l[BSn*Dn];
__device__ __half s_wa_h[N3D*Dn],  s_wa_l[N3D*Dn];   // transposed [N][K]
__device__ __half s_wp_h[Dn*Dn],   s_wp_l[Dn*Dn];    // transposed [N][K]
__device__ __half g_q_h[NQKV], g_q_l[NQKV];          // [bh][s][hd]
__device__ __half g_k_h[NQKV], g_k_l[NQKV];          // [bh][s][hd]
__device__ __half g_v_h[NQKV], g_v_l[NQKV];          // [bh][hd][s] (transposed)
__device__ __half g_att_h[NQKV], g_att_l[NQKV];      // [bh][s][hd]
__device__ __half g_w_h[(size_t)Bn*Hn*Sn*Sn];
__device__ __half g_w_l[(size_t)Bn*Hn*Sn*Sn];

// ---------------- helpers ----------------
__device__ __forceinline__ uint32_t s2u(const void* p) {
    return (uint32_t)__cvta_generic_to_shared(p);
}
__device__ __forceinline__ void ldsm4(uint32_t& r0, uint32_t& r1, uint32_t& r2,
                                      uint32_t& r3, uint32_t a) {
    asm volatile("ldmatrix.sync.aligned.m8n8.x4.shared.b16 {%0,%1,%2,%3},[%4];"
                 : "=r"(r0), "=r"(r1), "=r"(r2), "=r"(r3) : "r"(a));
}
// fp32-accumulate MMA (hi x hi term)
#define MMAF(c, a, b) asm volatile( \
    "mma.sync.aligned.m16n8k16.row.col.f32.f16.f16.f32 " \
    "{%0,%1,%2,%3},{%4,%5,%6,%7},{%8,%9},{%0,%1,%2,%3};" \
    : "+f"((c)[0]), "+f"((c)[1]), "+f"((c)[2]), "+f"((c)[3]) \
    : "r"((a)[0]), "r"((a)[1]), "r"((a)[2]), "r"((a)[3]), "r"((b)[0]), "r"((b)[1]))
// fp16-accumulate MMA (cross terms, full-rate path)
#define MMAH(c, a, b) asm volatile( \
    "mma.sync.aligned.m16n8k16.row.col.f16.f16.f16.f16 " \
    "{%0,%1},{%2,%3,%4,%5},{%6,%7},{%0,%1};" \
    : "+r"((c)[0]), "+r"((c)[1]) \
    : "r"((a)[0]), "r"((a)[1]), "r"((a)[2]), "r"((a)[3]), "r"((b)[0]), "r"((b)[1]))

__device__ __forceinline__ void cpa16(uint32_t dst, const void* src) {
    asm volatile("cp.async.cg.shared.global [%0], [%1], 16;" :: "r"(dst), "l"(src));
}
#define CP_COMMIT() asm volatile("cp.async.commit_group;")
#define CP_WAIT0()  asm volatile("cp.async.wait_group 0;")

// byte offset of 16B chunk c (0..7) in swizzled 128B row
__device__ __forceinline__ uint32_t swz(int row, int c) {
    return (uint32_t)row * 128u + (uint32_t)((c ^ (row & 7)) << 4);
}

// fp16 split: x = hi + lo, hi = fp16(x)
__device__ __forceinline__ void split2(float x, float y, uint32_t& ph, uint32_t& pl) {
    __half2 h2 = __floats2half2_rn(x, y);
    ph = *reinterpret_cast<uint32_t*>(&h2);
    __half2 l2 = __floats2half2_rn(x - __half2float(__low2half(h2)),
                                   y - __half2float(__high2half(h2)));
    pl = *reinterpret_cast<uint32_t*>(&l2);
}
__device__ __forceinline__ void split1(float x, __half& h, __half& l) {
    h = __float2half_rn(x);
    l = __float2half_rn(x - __half2float(h));
}

// one k32 sub-block, warp tile 64m x 16n.
// A at sub+0 (hi chunks 0-3, lo 4-7), B at sub+16384 (hi 0-3, lo 4-7, 64 rows).
__device__ __forceinline__ void cstage(uint32_t sub, float acc[4][2][4],
                                       uint32_t a16[4][2][2], int mbase, int nbase,
                                       int lane) {
    #pragma unroll
    for (int h = 0; h < 2; h++) {
        uint32_t bhf[2][2], blf[2][2];
        {
            int brow = nbase + (lane & 7) + ((lane >> 4) << 3);
            int bch = h * 2 + ((lane >> 3) & 1);
            uint32_t r0, r1, r2, r3;
            ldsm4(r0, r1, r2, r3, sub + 16384u + swz(brow, bch));
            bhf[0][0] = r0; bhf[0][1] = r1; bhf[1][0] = r2; bhf[1][1] = r3;
            ldsm4(r0, r1, r2, r3, sub + 16384u + swz(brow, bch + 4));
            blf[0][0] = r0; blf[0][1] = r1; blf[1][0] = r2; blf[1][1] = r3;
        }
        #pragma unroll
        for (int i = 0; i < 4; i++) {
            int arow = mbase + i * 16 + (lane & 15);
            int ach = h * 2 + (lane >> 4);
            uint32_t ah[4], al[4];
            ldsm4(ah[0], ah[1], ah[2], ah[3], sub + swz(arow, ach));
            ldsm4(al[0], al[1], al[2], al[3], sub + swz(arow, ach + 4));
            #pragma unroll
            for (int j = 0; j < 2; j++) {
                MMAF(acc[i][j], ah, bhf[j]);
                MMAH(a16[i][j], ah, blf[j]);
                MMAH(a16[i][j], al, bhf[j]);
            }
        }
    }
}

// combine fp32 acc + fp16 cross acc -> 2 floats (elements half*2, half*2+1)
__device__ __forceinline__ void comb(const float* a32, const uint32_t* a16,
                                     int half, float& v0, float& v1) {
    __half2 e = *reinterpret_cast<const __half2*>(&a16[half]);
    v0 = a32[half * 2 + 0] + __half2float(__low2half(e));
    v1 = a32[half * 2 + 1] + __half2float(__high2half(e));
}

// ---------------------------------------------------------------------------
// Kernel 0a/0b: input splits.
// ---------------------------------------------------------------------------
__global__ __launch_bounds__(256) void split_hs(const float* __restrict__ hs) {
    int i = (blockIdx.x * 256 + threadIdx.x) * 4;
    float4 v = *(const float4*)&hs[i];
    uint32_t ph0, pl0, ph1, pl1;
    split2(v.x, v.y, ph0, pl0);
    split2(v.z, v.w, ph1, pl1);
    *(uint2*)&s_hs_h[i] = make_uint2(ph0, ph1);
    *(uint2*)&s_hs_l[i] = make_uint2(pl0, pl1);
}

__global__ __launch_bounds__(256) void split_transpose(const float* __restrict__ in,
                                                       __half* __restrict__ oh,
                                                       __half* __restrict__ ol,
                                                       int K, int N) {
    __shared__ float t[32][33];
    int nb = blockIdx.x * 32, kb = blockIdx.y * 32;
    int tx = threadIdx.x & 31, ty = threadIdx.x >> 5;
    #pragma unroll
    for (int i = 0; i < 4; i++) {
        int r = ty + i * 8;
        t[r][tx] = in[(size_t)(kb + r) * N + nb + tx];
    }
    __syncthreads();
    #pragma unroll
    for (int i = 0; i < 4; i++) {
        int r = ty + i * 8;
        float v = t[tx][r];
        __half h, l; split1(v, h, l);
        size_t o = (size_t)(nb + r) * K + kb + tx;
        oh[o] = h; ol[o] = l;
    }
}

// ---------------------------------------------------------------------------
// Kernel 1: QKV projection. 128m x 64n, warp 64x16, k64 x 16 stages, 2 slots.
// ---------------------------------------------------------------------------
__global__ __launch_bounds__(256, 2) void qkv_gemm(const float* __restrict__ bias) {
    extern __shared__ __align__(16) char dynsmem[];
    const uint32_t smb = s2u(dynsmem);
    const int K = 1024;
    int tid = threadIdx.x, lane = tid & 31, wid = tid >> 5;
    int row0 = blockIdx.y * 128, col0 = blockIdx.x * 64;
    int mbase = (wid & 1) * 64, nbase = (wid >> 1) * 16;
    int srow = tid >> 1, sh = tid & 1;
    int brow = tid >> 2, bq = tid & 3;
    const __half* gAh = s_hs_h + (size_t)(row0 + srow) * K + sh * 16;
    const __half* gAl = s_hs_l + (size_t)(row0 + srow) * K + sh * 16;
    const __half* gBh = s_wa_h + (size_t)(col0 + brow) * K + bq * 8;
    const __half* gBl = s_wa_l + (size_t)(col0 + brow) * K + bq * 8;
    uint32_t dA0 = swz(srow, sh * 2),     dA1 = swz(srow, sh * 2 + 1);
    uint32_t dL0 = swz(srow, sh * 2 + 4), dL1 = swz(srow, sh * 2 + 5);
    uint32_t dB0 = 16384u + swz(brow, bq), dB1 = 16384u + swz(brow, bq + 4);

    float acc[4][2][4] = {};
    uint32_t a16[4][2][2] = {};
    const int T = K / 64;   // 16 stages

    #define QSUB(sb, koff) do { \
        cpa16((sb) + dA0, gAh + (koff));  cpa16((sb) + dA1, gAh + (koff) + 8); \
        cpa16((sb) + dL0, gAl + (koff));  cpa16((sb) + dL1, gAl + (koff) + 8); \
        cpa16((sb) + dB0, gBh + (koff));  cpa16((sb) + dB1, gBl + (koff)); } while (0)
    #define QISSUE(t) do { uint32_t sb = smb + ((t) & 1) * SLOT_G; \
        QSUB(sb, (t) * 64); QSUB(sb + SUB_G, (t) * 64 + 32); } while (0)

    QISSUE(0); CP_COMMIT();
    for (int t = 0; t < T; t++) {
        CP_WAIT0();
        __syncthreads();
        if (t + 1 < T) QISSUE(t + 1);
        CP_COMMIT();
        uint32_t sb = smb + (t & 1) * SLOT_G;
        cstage(sb, acc, a16, mbase, nbase, lane);
        cstage(sb + SUB_G, acc, a16, mbase, nbase, lane);
    }
    #undef QISSUE
    #undef QSUB

    #pragma unroll
    for (int i = 0; i < 4; i++) {
        #pragma unroll
        for (int j = 0; j < 2; j++) {
            int rr = row0 + mbase + i * 16 + (lane >> 2);
            int cc = col0 + nbase + j * 8 + (lane & 3) * 2;
            #pragma unroll
            for (int half = 0; half < 2; half++) {
                int r = rr + half * 8;
                int b = r >> 11, s = r & 2047;
                float v0, v1;
                comb(acc[i][j], a16[i][j], half, v0, v1);
                v0 += bias[cc]; v1 += bias[cc + 1];
                uint32_t ph, pl; split2(v0, v1, ph, pl);
                int which = cc >> 10;
                int dcol = cc & 1023;
                int h = dcol >> 6, hd = dcol & 63;
                int bh = b * Hn + h;
                if (which == 0) {
                    size_t idx = ((size_t)bh * Sn + s) * HDn + hd;
                    *(uint32_t*)&g_q_h[idx] = ph; *(uint32_t*)&g_q_l[idx] = pl;
                } else if (which == 1) {
                    size_t idx = ((size_t)bh * Sn + s) * HDn + hd;
                    *(uint32_t*)&g_k_h[idx] = ph; *(uint32_t*)&g_k_l[idx] = pl;
                } else {
                    size_t i0 = ((size_t)bh * HDn + hd) * Sn + s;
                    size_t i1 = ((size_t)bh * HDn + hd + 1) * Sn + s;
                    ((uint16_t*)g_v_h)[i0] = (uint16_t)(ph & 0xffff);
                    ((uint16_t*)g_v_h)[i1] = (uint16_t)(ph >> 16);
                    ((uint16_t*)g_v_l)[i0] = (uint16_t)(pl & 0xffff);
                    ((uint16_t*)g_v_l)[i1] = (uint16_t)(pl >> 16);
                }
            }
        }
    }
}

// ---------------------------------------------------------------------------
// Kernel 2: raw scores, lower-tri 128q x 64k tiles, K=64 single-shot.
// grid.x = 272 per bh: cum(qb) = qb^2+qb, kb in [0, 2qb+2).
// ---------------------------------------------------------------------------
__global__ __launch_bounds__(256, 2) void scores_kernel(const float* __restrict__ mask,
                                                        float* __restrict__ Wout) {
    extern __shared__ __align__(16) char dynsmem[];
    const uint32_t smb = s2u(dynsmem);
    int idx = blockIdx.x;
    int qb = (int)((sqrtf(4.0f * idx + 1.0f) - 1.0f) * 0.5f);
    while ((qb + 1) * (qb + 2) <= idx) qb++;
    while (qb * (qb + 1) > idx) qb--;
    int kb = idx - qb * (qb + 1);
    int bh = blockIdx.y;
    int bb = bh >> 4;
    int tid = threadIdx.x, lane = tid & 31, wid = tid >> 5;
    int row0 = qb * 128, col0 = kb * 64;
    int mbase = (wid & 1) * 64, nbase = (wid >> 1) * 16;
    int srow = tid >> 1, sh = tid & 1;
    int brow = tid >> 2, bq = tid & 3;
    const __half* gAh = g_q_h + ((size_t)bh * Sn + row0 + srow) * HDn + sh * 16;
    const __half* gAl = g_q_l + ((size_t)bh * Sn + row0 + srow) * HDn + sh * 16;
    const __half* gBh = g_k_h + ((size_t)bh * Sn + col0 + brow) * HDn + bq * 8;
    const __half* gBl = g_k_l + ((size_t)bh * Sn + col0 + brow) * HDn + bq * 8;
    uint32_t dA0 = swz(srow, sh * 2),     dA1 = swz(srow, sh * 2 + 1);
    uint32_t dL0 = swz(srow, sh * 2 + 4), dL1 = swz(srow, sh * 2 + 5);
    uint32_t dB0 = 16384u + swz(brow, bq), dB1 = 16384u + swz(brow, bq + 4);

    #pragma unroll
    for (int s = 0; s < 2; s++) {
        uint32_t sb = smb + s * SUB_G;
        int koff = s * 32;
        cpa16(sb + dA0, gAh + koff);  cpa16(sb + dA1, gAh + koff + 8);
        cpa16(sb + dL0, gAl + koff);  cpa16(sb + dL1, gAl + koff + 8);
        cpa16(sb + dB0, gBh + koff);  cpa16(sb + dB1, gBl + koff);
    }
    CP_COMMIT();
    CP_WAIT0();
    __syncthreads();

    float acc[4][2][4] = {};
    uint32_t a16[4][2][2] = {};
    cstage(smb, acc, a16, mbase, nbase, lane);
    cstage(smb + SUB_G, acc, a16, mbase, nbase, lane);

    const float scale = 0.125f;
    #pragma unroll
    for (int i = 0; i < 4; i++) {
        #pragma unroll
        for (int j = 0; j < 2; j++) {
            int rr = row0 + mbase + i * 16 + (lane >> 2);
            int cc = col0 + nbase + j * 8 + (lane & 3) * 2;
            #pragma unroll
            for (int half = 0; half < 2; half++) {
                int r = rr + half * 8;
                float v0, v1;
                comb(acc[i][j], a16[i][j], half, v0, v1);
                float* orow = Wout + ((size_t)bh * Sn + r) * Sn;
                orow[cc]     = v0 * scale + mask[bb * Sn + cc];
                orow[cc + 1] = v1 * scale + mask[bb * Sn + cc + 1];
            }
        }
    }
}

// ---------------------------------------------------------------------------
// Kernel 3: row softmax (fp16 split writes).
// ---------------------------------------------------------------------------
__global__ __launch_bounds__(256) void softmax_kernel(float* __restrict__ Wm) {
    __shared__ float buf[Sn];
    __shared__ float red[8];
    int row = blockIdx.x;
    int q = row & (Sn - 1);
    int len = q + 1;
    int blockend = ((q >> 7) + 1) << 7;
    float* wrow = Wm + (size_t)row * Sn;
    size_t wb = (size_t)row * Sn;
    int tid = threadIdx.x;
    int lane = tid & 31, warp = tid >> 5;

    float mx = -1e30f;
    for (int c = tid * 4; c < blockend; c += 1024) {
        float4 v = *(const float4*)&wrow[c];
        *(float4*)&buf[c] = v;
        if (c + 3 < len) {
            mx = fmaxf(mx, fmaxf(fmaxf(v.x, v.y), fmaxf(v.z, v.w)));
        } else {
            if (c     < len) mx = fmaxf(mx, v.x);
            if (c + 1 < len) mx = fmaxf(mx, v.y);
            if (c + 2 < len) mx = fmaxf(mx, v.z);
            if (c + 3 < len) mx = fmaxf(mx, v.w);
        }
    }
    #pragma unroll
    for (int o = 16; o > 0; o >>= 1) mx = fmaxf(mx, __shfl_xor_sync(0xffffffffu, mx, o));
    if (lane == 0) red[warp] = mx;
    __syncthreads();
    if (tid < 32) {
        float t = (tid < 8) ? red[tid] : -1e30f;
        #pragma unroll
        for (int o = 4; o > 0; o >>= 1) t = fmaxf(t, __shfl_xor_sync(0xffffffffu, t, o));
        if (tid == 0) red[0] = t;
    }
    __syncthreads();
    mx = red[0];
    __syncthreads();

    float sum = 0.0f;
    for (int c = tid * 4; c < blockend; c += 1024) {
        float4 v = *(const float4*)&buf[c];
        float e0 = (c     < len) ? __expf(v.x - mx) : 0.0f;
        float e1 = (c + 1 < len) ? __expf(v.y - mx) : 0.0f;
        float e2 = (c + 2 < len) ? __expf(v.z - mx) : 0.0f;
        float e3 = (c + 3 < len) ? __expf(v.w - mx) : 0.0f;
        sum += (e0 + e1) + (e2 + e3);
        *(float4*)&buf[c] = make_float4(e0, e1, e2, e3);
    }
    #pragma unroll
    for (int o = 16; o > 0; o >>= 1) sum += __shfl_xor_sync(0xffffffffu, sum, o);
    if (lane == 0) red[warp] = sum;
    __syncthreads();
    if (tid < 32) {
        float t = (tid < 8) ? red[tid] : 0.0f;
        #pragma unroll
        for (int o = 4; o > 0; o >>= 1) t += __shfl_xor_sync(0xffffffffu, t, o);
        if (tid == 0) red[0] = t;
    }
    __syncthreads();
    float inv = 1.0f / red[0];

    for (int c = tid * 4; c < blockend; c += 1024) {
        float4 v = *(const float4*)&buf[c];
        v.x *= inv; v.y *= inv; v.z *= inv; v.w *= inv;
        *(float4*)&wrow[c] = v;
        uint32_t ph0, pl0, ph1, pl1;
        split2(v.x, v.y, ph0, pl0);
        split2(v.z, v.w, ph1, pl1);
        *(uint2*)&g_w_h[wb + c] = make_uint2(ph0, ph1);
        *(uint2*)&g_w_l[wb + c] = make_uint2(pl0, pl1);
    }
    for (int c = blockend + tid * 4; c < Sn; c += 1024)
        *(float4*)&wrow[c] = make_float4(0.f, 0.f, 0.f, 0.f);
}

// ---------------------------------------------------------------------------
// Kernel 4: attn_heads = weights @ V. 128m x 64n, warp 64x16, k64 stages.
// ---------------------------------------------------------------------------
__global__ __launch_bounds__(256, 2) void av_kernel() {
    extern __shared__ __align__(16) char dynsmem[];
    const uint32_t smb = s2u(dynsmem);
    int qb = gridDim.x - 1 - blockIdx.x;   // longest first
    int bh = blockIdx.y;
    int tid = threadIdx.x, lane = tid & 31, wid = tid >> 5;
    int row0 = qb * 128;
    int mbase = (wid & 1) * 64, nbase = (wid >> 1) * 16;
    int srow = tid >> 1, sh = tid & 1;
    int brow = tid >> 2, bq = tid & 3;
    const __half* gAh = g_w_h + (size_t)bh * Sn * Sn + (size_t)(row0 + srow) * Sn + sh * 16;
    const __half* gAl = g_w_l + (size_t)bh * Sn * Sn + (size_t)(row0 + srow) * Sn + sh * 16;
    const __half* gBh = g_v_h + ((size_t)bh * HDn + brow) * Sn + bq * 8;
    const __half* gBl = g_v_l + ((size_t)bh * HDn + brow) * Sn + bq * 8;
    uint32_t dA0 = swz(srow, sh * 2),     dA1 = swz(srow, sh * 2 + 1);
    uint32_t dL0 = swz(srow, sh * 2 + 4), dL1 = swz(srow, sh * 2 + 5);
    uint32_t dB0 = 16384u + swz(brow, bq), dB1 = 16384u + swz(brow, bq + 4);

    float acc[4][2][4] = {};
    uint32_t a16[4][2][2] = {};
    const int T = (qb + 1) * 2;   // k64 stages over causal prefix

    #define ASUB(sb, koff) do { \
        cpa16((sb) + dA0, gAh + (koff));  cpa16((sb) + dA1, gAh + (koff) + 8); \
        cpa16((sb) + dL0, gAl + (koff));  cpa16((sb) + dL1, gAl + (koff) + 8); \
        cpa16((sb) + dB0, gBh + (koff));  cpa16((sb) + dB1, gBl + (koff)); } while (0)
    #define AISSUE(t) do { uint32_t sb = smb + ((t) & 1) * SLOT_G; \
        ASUB(sb, (t) * 64); ASUB(sb + SUB_G, (t) * 64 + 32); } while (0)

    AISSUE(0); CP_COMMIT();
    for (int t = 0; t < T; t++) {
        CP_WAIT0();
        __syncthreads();
        if (t + 1 < T) AISSUE(t + 1);
        CP_COMMIT();
        uint32_t sb = smb + (t & 1) * SLOT_G;
        cstage(sb, acc, a16, mbase, nbase, lane);
        cstage(sb + SUB_G, acc, a16, mbase, nbase, lane);
    }
    #undef AISSUE
    #undef ASUB

    #pragma unroll
    for (int i = 0; i < 4; i++) {
        #pragma unroll
        for (int j = 0; j < 2; j++) {
            int rr = row0 + mbase + i * 16 + (lane >> 2);
            int cc = nbase + j * 8 + (lane & 3) * 2;
            #pragma unroll
            for (int half = 0; half < 2; half++) {
                int r = rr + half * 8;
                float v0, v1;
                comb(acc[i][j], a16[i][j], half, v0, v1);
                uint32_t ph, pl; split2(v0, v1, ph, pl);
                size_t idx = ((size_t)bh * Sn + r) * HDn + cc;
                *(uint32_t*)&g_att_h[idx] = ph;
                *(uint32_t*)&g_att_l[idx] = pl;
            }
        }
    }
}

// ---------------------------------------------------------------------------
// Kernel 5: output projection. 128m x 64n, k64 stages (stage t = head t).
// ---------------------------------------------------------------------------
__global__ __launch_bounds__(256, 2) void proj_gemm(const float* __restrict__ bias,
                                                    float* __restrict__ out) {
    extern __shared__ __align__(16) char dynsmem[];
    const uint32_t smb = s2u(dynsmem);
    const int K = 1024, N = 1024;
    int tid = threadIdx.x, lane = tid & 31, wid = tid >> 5;
    int row0 = blockIdx.y * 128, col0 = blockIdx.x * 64;
    int mbase = (wid & 1) * 64, nbase = (wid >> 1) * 16;
    int srow = tid >> 1, sh = tid & 1;
    int brow = tid >> 2, bq = tid & 3;
    int arow = row0 + srow;
    int ab = arow >> 11, as = arow & 2047;
    size_t abase = (((size_t)ab * Hn) * Sn + as) * HDn + sh * 16;  // + head*Sn*HDn
    const __half* gBh = s_wp_h + (size_t)(col0 + brow) * K + bq * 8;
    const __half* gBl = s_wp_l + (size_t)(col0 + brow) * K + bq * 8;
    uint32_t dA0 = swz(srow, sh * 2),     dA1 = swz(srow, sh * 2 + 1);
    uint32_t dL0 = swz(srow, sh * 2 + 4), dL1 = swz(srow, sh * 2 + 5);
    uint32_t dB0 = 16384u + swz(brow, bq), dB1 = 16384u + swz(brow, bq + 4);

    float acc[4][2][4] = {};
    uint32_t a16[4][2][2] = {};
    const int T = K / 64;   // 16 stages; stage t = head t

    #define PSUB(sb, so, koff) do { \
        cpa16((sb) + dA0, g_att_h + (so));  cpa16((sb) + dA1, g_att_h + (so) + 8); \
        cpa16((sb) + dL0, g_att_l + (so));  cpa16((sb) + dL1, g_att_l + (so) + 8); \
        cpa16((sb) + dB0, gBh + (koff));    cpa16((sb) + dB1, gBl + (koff)); } while (0)
    #define PISSUE(t) do { uint32_t sb = smb + ((t) & 1) * SLOT_G; \
        size_t so = abase + (size_t)(t) * Sn * HDn; \
        PSUB(sb, so, (t) * 64); PSUB(sb + SUB_G, so + 32, (t) * 64 + 32); } while (0)

    PISSUE(0); CP_COMMIT();
    for (int t = 0; t < T; t++) {
        CP_WAIT0();
        __syncthreads();
        if (t + 1 < T) PISSUE(t + 1);
        CP_COMMIT();
        uint32_t sb = smb + (t & 1) * SLOT_G;
        cstage(sb, acc, a16, mbase, nbase, lane);
        cstage(sb + SUB_G, acc, a16, mbase, nbase, lane);
    }
    #undef PISSUE
    #undef PSUB

    #pragma unroll
    for (int i = 0; i < 4; i++) {
        #pragma unroll
        for (int j = 0; j < 2; j++) {
            int rr = row0 + mbase + i * 16 + (lane >> 2);
            int cc = col0 + nbase + j * 8 + (lane & 3) * 2;
            #pragma unroll
            for (int half = 0; half < 2; half++) {
                int r = rr + half * 8;
                float v0, v1;
                comb(acc[i][j], a16[i][j], half, v0, v1);
                out[(size_t)r * N + cc]     = v0 + bias[cc];
                out[(size_t)r * N + cc + 1] = v1 + bias[cc + 1];
            }
        }
    }
}

// ---------------------------------------------------------------------------
extern "C" void kernel_launch(void* const* d_in, const int* in_sizes, int n_in,
                              void* d_out, int out_size) {
    (void)in_sizes; (void)n_in; (void)out_size;
    const float* hs     = (const float*)d_in[0];
    const float* mask   = (const float*)d_in[1];
    const float* w_attn = (const float*)d_in[2];
    const float* b_attn = (const float*)d_in[3];
    const float* w_proj = (const float*)d_in[4];
    const float* b_proj = (const float*)d_in[5];

    float* attn_out = (float*)d_out;                          // [B,S,D]
    float* weights  = (float*)d_out + (size_t)Bn * Sn * Dn;   // [B,H,S,S]

    cudaFuncSetAttribute(qkv_gemm,      cudaFuncAttributeMaxDynamicSharedMemorySize, SMEM_G);
    cudaFuncSetAttribute(scores_kernel, cudaFuncAttributeMaxDynamicSharedMemorySize, SMEM_SC);
    cudaFuncSetAttribute(av_kernel,     cudaFuncAttributeMaxDynamicSharedMemorySize, SMEM_G);
    cudaFuncSetAttribute(proj_gemm,     cudaFuncAttributeMaxDynamicSharedMemorySize, SMEM_G);

    __half *wa_h, *wa_l, *wp_h, *wp_l;
    cudaGetSymbolAddress((void**)&wa_h, s_wa_h);
    cudaGetSymbolAddress((void**)&wa_l, s_wa_l);
    cudaGetSymbolAddress((void**)&wp_h, s_wp_h);
    cudaGetSymbolAddress((void**)&wp_l, s_wp_l);

    split_hs<<<BSn * Dn / 1024, 256>>>(hs);
    split_transpose<<<dim3(N3D / 32, Dn / 32), 256>>>(w_attn, wa_h, wa_l, Dn, N3D);
    split_transpose<<<dim3(Dn / 32, Dn / 32), 256>>>(w_proj, wp_h, wp_l, Dn, Dn);
    qkv_gemm<<<dim3(N3D / 64, BSn / 128), 256, SMEM_G>>>(b_attn);
    scores_kernel<<<dim3(272, Bn * Hn), 256, SMEM_SC>>>(mask, weights);
    softmax_kernel<<<dim3(Bn * Hn * Sn), 256>>>(weights);
    av_kernel<<<dim3(Sn / 128, Bn * Hn), 256, SMEM_G>>>();
    proj_gemm<<<dim3(Dn / 64, BSn / 128), 256, SMEM_G>>>(b_proj, attn_out);
}

// round 10
// speedup vs baseline: 1.1893x; 1.1893x over previous
#include <cuda_runtime.h>
#include <cuda_fp16.h>
#include <math.h>
#include <stdint.h>

#define Bn 2
#define Sn 2048
#define Dn 1024
#define Hn 16
#define HDn 64
#define BSn (Bn*Sn)      // 4096
#define N3D (3*Dn)       // 3072
#define NQKV (Bn*Hn*Sn*HDn)

// k64-stage layouts:
//  wide (split A, single B): Ah 16KB | Al 16KB | Bh 8KB  -> 40KB/stage
//  av   (single A, split B): Ah 16KB | Bh 8KB  | Bl 8KB  -> 32KB/stage
#define SLOT_W  40960
#define SLOT_AV 32768
#define SMEM_W  (2*SLOT_W)    // 81920 -> 2 CTAs/SM
#define SMEM_AV (2*SLOT_AV)   // 65536
#define SMEM_SC SLOT_W        // scores: single-shot K=64

// ---------------- fp16 scratch (device globals) ----------------
__device__ __half s_hs_h[BSn*Dn],  s_hs_l[BSn*Dn];   // hidden states split
__device__ __half s_wa_h[N3D*Dn];                    // w_attn^T single
__device__ __half s_wp_h[Dn*Dn];                     // w_proj^T single
__device__ __half g_q_h[NQKV], g_q_l[NQKV];          // q split   [bh][s][hd]
__device__ __half g_k_h[NQKV];                       // k single  [bh][s][hd]
__device__ __half g_v_h[NQKV], g_v_l[NQKV];          // v split   [bh][hd][s]
__device__ __half g_att_h[NQKV], g_att_l[NQKV];      // att split [bh][s][hd]
__device__ __half g_w_h[(size_t)Bn*Hn*Sn*Sn];        // weights single

// ---------------- helpers ----------------
__device__ __forceinline__ uint32_t s2u(const void* p) {
    return (uint32_t)__cvta_generic_to_shared(p);
}
__device__ __forceinline__ void ldsm4(uint32_t& r0, uint32_t& r1, uint32_t& r2,
                                      uint32_t& r3, uint32_t a) {
    asm volatile("ldmatrix.sync.aligned.m8n8.x4.shared.b16 {%0,%1,%2,%3},[%4];"
                 : "=r"(r0), "=r"(r1), "=r"(r2), "=r"(r3) : "r"(a));
}
#define MMAF(c, a, b) asm volatile( \
    "mma.sync.aligned.m16n8k16.row.col.f32.f16.f16.f32 " \
    "{%0,%1,%2,%3},{%4,%5,%6,%7},{%8,%9},{%0,%1,%2,%3};" \
    : "+f"((c)[0]), "+f"((c)[1]), "+f"((c)[2]), "+f"((c)[3]) \
    : "r"((a)[0]), "r"((a)[1]), "r"((a)[2]), "r"((a)[3]), "r"((b)[0]), "r"((b)[1]))

__device__ __forceinline__ void cpa16(uint32_t dst, const void* src) {
    asm volatile("cp.async.cg.shared.global [%0], [%1], 16;" :: "r"(dst), "l"(src));
}
#define CP_COMMIT() asm volatile("cp.async.commit_group;")
#define CP_WAIT0()  asm volatile("cp.async.wait_group 0;")

// byte offset of 16B chunk c (0..7) in swizzled 128B row (row covers k64 halves)
__device__ __forceinline__ uint32_t swz(int row, int c) {
    return (uint32_t)row * 128u + (uint32_t)((c ^ (row & 7)) << 4);
}

// fp16 split: x = hi + lo
__device__ __forceinline__ void split2(float x, float y, uint32_t& ph, uint32_t& pl) {
    __half2 h2 = __floats2half2_rn(x, y);
    ph = *reinterpret_cast<uint32_t*>(&h2);
    __half2 l2 = __floats2half2_rn(x - __half2float(__low2half(h2)),
                                   y - __half2float(__high2half(h2)));
    pl = *reinterpret_cast<uint32_t*>(&l2);
}
__device__ __forceinline__ uint32_t pack2(float x, float y) {
    __half2 h2 = __floats2half2_rn(x, y);
    return *reinterpret_cast<uint32_t*>(&h2);
}

// wide stage (k64): split A (Ah @0, Al @16384), single B (Bh @32768)
__device__ __forceinline__ void cstage_w(uint32_t sb, float acc[4][2][4],
                                         int mbase, int nbase, int lane) {
    #pragma unroll
    for (int kk = 0; kk < 4; kk++) {
        uint32_t bf[2][2];
        {
            int brow = nbase + (lane & 7) + ((lane >> 4) << 3);
            int bch = kk * 2 + ((lane >> 3) & 1);
            uint32_t r0, r1, r2, r3;
            ldsm4(r0, r1, r2, r3, sb + 32768u + swz(brow, bch));
            bf[0][0] = r0; bf[0][1] = r1; bf[1][0] = r2; bf[1][1] = r3;
        }
        #pragma unroll
        for (int i = 0; i < 4; i++) {
            int arow = mbase + i * 16 + (lane & 15);
            int ach = kk * 2 + (lane >> 4);
            uint32_t ah[4], al[4];
            ldsm4(ah[0], ah[1], ah[2], ah[3], sb + swz(arow, ach));
            ldsm4(al[0], al[1], al[2], al[3], sb + 16384u + swz(arow, ach));
            #pragma unroll
            for (int j = 0; j < 2; j++) {
                MMAF(acc[i][j], ah, bf[j]);
                MMAF(acc[i][j], al, bf[j]);
            }
        }
    }
}

// av stage (k64): single A (Ah @0), split B (Bh @16384, Bl @24576)
__device__ __forceinline__ void cstage_av(uint32_t sb, float acc[4][2][4],
                                          int mbase, int nbase, int lane) {
    #pragma unroll
    for (int kk = 0; kk < 4; kk++) {
        uint32_t bhf[2][2], blf[2][2];
        {
            int brow = nbase + (lane & 7) + ((lane >> 4) << 3);
            int bch = kk * 2 + ((lane >> 3) & 1);
            uint32_t r0, r1, r2, r3;
            ldsm4(r0, r1, r2, r3, sb + 16384u + swz(brow, bch));
            bhf[0][0] = r0; bhf[0][1] = r1; bhf[1][0] = r2; bhf[1][1] = r3;
            ldsm4(r0, r1, r2, r3, sb + 24576u + swz(brow, bch));
            blf[0][0] = r0; blf[0][1] = r1; blf[1][0] = r2; blf[1][1] = r3;
        }
        #pragma unroll
        for (int i = 0; i < 4; i++) {
            int arow = mbase + i * 16 + (lane & 15);
            int ach = kk * 2 + (lane >> 4);
            uint32_t ah[4];
            ldsm4(ah[0], ah[1], ah[2], ah[3], sb + swz(arow, ach));
            #pragma unroll
            for (int j = 0; j < 2; j++) {
                MMAF(acc[i][j], ah, bhf[j]);
                MMAF(acc[i][j], ah, blf[j]);
            }
        }
    }
}

// ---------------------------------------------------------------------------
// Kernel 0a: split hidden states (h + l).
// ---------------------------------------------------------------------------
__global__ __launch_bounds__(256) void split_hs(const float* __restrict__ hs) {
    int i = (blockIdx.x * 256 + threadIdx.x) * 4;
    float4 v = *(const float4*)&hs[i];
    uint32_t ph0, pl0, ph1, pl1;
    split2(v.x, v.y, ph0, pl0);
    split2(v.z, v.w, ph1, pl1);
    *(uint2*)&s_hs_h[i] = make_uint2(ph0, ph1);
    *(uint2*)&s_hs_l[i] = make_uint2(pl0, pl1);
}

// ---------------------------------------------------------------------------
// Kernel 0b: tiled transpose of [K,N] weight -> single fp16 [N,K].
// ---------------------------------------------------------------------------
__global__ __launch_bounds__(256) void split_transpose(const float* __restrict__ in,
                                                       __half* __restrict__ oh,
                                                       int K, int N) {
    __shared__ float t[32][33];
    int nb = blockIdx.x * 32, kb = blockIdx.y * 32;
    int tx = threadIdx.x & 31, ty = threadIdx.x >> 5;
    #pragma unroll
    for (int i = 0; i < 4; i++) {
        int r = ty + i * 8;
        t[r][tx] = in[(size_t)(kb + r) * N + nb + tx];
    }
    __syncthreads();
    #pragma unroll
    for (int i = 0; i < 4; i++) {
        int r = ty + i * 8;
        oh[(size_t)(nb + r) * K + kb + tx] = __float2half_rn(t[tx][r]);
    }
}

// ---------------------------------------------------------------------------
// Kernel 1: QKV projection. 128m x 64n, warp 64x16, k64 x 16 stages.
// A = hs split, B = w_attn single.
// ---------------------------------------------------------------------------
__global__ __launch_bounds__(256, 2) void qkv_gemm(const float* __restrict__ bias) {
    extern __shared__ __align__(16) char dynsmem[];
    const uint32_t smb = s2u(dynsmem);
    const int K = 1024;
    int tid = threadIdx.x, lane = tid & 31, wid = tid >> 5;
    int row0 = blockIdx.y * 128, col0 = blockIdx.x * 64;
    int mbase = (wid & 1) * 64, nbase = (wid >> 1) * 16;
    int srow = tid >> 1, sh = tid & 1;          // A loader: 2 threads/row, 64B each
    int brow = tid >> 2, bq = tid & 3;          // B loader: 4 threads/row, 32B each
    const __half* gAh = s_hs_h + (size_t)(row0 + srow) * K + sh * 32;
    const __half* gAl = s_hs_l + (size_t)(row0 + srow) * K + sh * 32;
    const __half* gB  = s_wa_h + (size_t)(col0 + brow) * K + bq * 16;
    uint32_t dA[4];
    #pragma unroll
    for (int i = 0; i < 4; i++) dA[i] = swz(srow, sh * 4 + i);
    uint32_t dB0 = 32768u + swz(brow, bq * 2), dB1 = 32768u + swz(brow, bq * 2 + 1);

    float acc[4][2][4] = {};
    const int T = K / 64;   // 16 stages

    #define QISSUE(t) do { uint32_t sb = smb + ((t) & 1) * SLOT_W; \
        _Pragma("unroll") for (int i = 0; i < 4; i++) { \
            cpa16(sb + dA[i],          gAh + (t) * 64 + i * 8); \
            cpa16(sb + 16384 + dA[i],  gAl + (t) * 64 + i * 8); } \
        cpa16(sb + dB0, gB + (t) * 64);  cpa16(sb + dB1, gB + (t) * 64 + 8); } while (0)

    QISSUE(0); CP_COMMIT();
    for (int t = 0; t < T; t++) {
        CP_WAIT0();
        __syncthreads();
        if (t + 1 < T) QISSUE(t + 1);
        CP_COMMIT();
        cstage_w(smb + (t & 1) * SLOT_W, acc, mbase, nbase, lane);
    }
    #undef QISSUE

    #pragma unroll
    for (int i = 0; i < 4; i++) {
        #pragma unroll
        for (int j = 0; j < 2; j++) {
            int rr = row0 + mbase + i * 16 + (lane >> 2);
            int cc = col0 + nbase + j * 8 + (lane & 3) * 2;
            #pragma unroll
            for (int half = 0; half < 2; half++) {
                int r = rr + half * 8;
                int b = r >> 11, s = r & 2047;
                float v0 = acc[i][j][half * 2 + 0] + bias[cc];
                float v1 = acc[i][j][half * 2 + 1] + bias[cc + 1];
                int which = cc >> 10;
                int dcol = cc & 1023;
                int h = dcol >> 6, hd = dcol & 63;
                int bh = b * Hn + h;
                if (which == 0) {          // q: split
                    uint32_t ph, pl; split2(v0, v1, ph, pl);
                    size_t idx = ((size_t)bh * Sn + s) * HDn + hd;
                    *(uint32_t*)&g_q_h[idx] = ph; *(uint32_t*)&g_q_l[idx] = pl;
                } else if (which == 1) {   // k: single
                    size_t idx = ((size_t)bh * Sn + s) * HDn + hd;
                    *(uint32_t*)&g_k_h[idx] = pack2(v0, v1);
                } else {                   // v: split, transposed [bh][hd][s]
                    uint32_t ph, pl; split2(v0, v1, ph, pl);
                    size_t i0 = ((size_t)bh * HDn + hd) * Sn + s;
                    size_t i1 = ((size_t)bh * HDn + hd + 1) * Sn + s;
                    ((uint16_t*)g_v_h)[i0] = (uint16_t)(ph & 0xffff);
                    ((uint16_t*)g_v_h)[i1] = (uint16_t)(ph >> 16);
                    ((uint16_t*)g_v_l)[i0] = (uint16_t)(pl & 0xffff);
                    ((uint16_t*)g_v_l)[i1] = (uint16_t)(pl >> 16);
                }
            }
        }
    }
}

// ---------------------------------------------------------------------------
// Kernel 2: raw scores, lower-tri 128q x 64k tiles, K=64 single-shot.
// A = q split, B = k single.
// ---------------------------------------------------------------------------
__global__ __launch_bounds__(256, 2) void scores_kernel(const float* __restrict__ mask,
                                                        float* __restrict__ Wout) {
    extern __shared__ __align__(16) char dynsmem[];
    const uint32_t smb = s2u(dynsmem);
    int idx = blockIdx.x;
    int qb = (int)((sqrtf(4.0f * idx + 1.0f) - 1.0f) * 0.5f);
    while ((qb + 1) * (qb + 2) <= idx) qb++;
    while (qb * (qb + 1) > idx) qb--;
    int kb = idx - qb * (qb + 1);
    int bh = blockIdx.y;
    int bb = bh >> 4;
    int tid = threadIdx.x, lane = tid & 31, wid = tid >> 5;
    int row0 = qb * 128, col0 = kb * 64;
    int mbase = (wid & 1) * 64, nbase = (wid >> 1) * 16;
    int srow = tid >> 1, sh = tid & 1;
    int brow = tid >> 2, bq = tid & 3;
    const __half* gAh = g_q_h + ((size_t)bh * Sn + row0 + srow) * HDn + sh * 32;
    const __half* gAl = g_q_l + ((size_t)bh * Sn + row0 + srow) * HDn + sh * 32;
    const __half* gB  = g_k_h + ((size_t)bh * Sn + col0 + brow) * HDn + bq * 16;

    #pragma unroll
    for (int i = 0; i < 4; i++) {
        uint32_t d = swz(srow, sh * 4 + i);
        cpa16(smb + d,          gAh + i * 8);
        cpa16(smb + 16384 + d,  gAl + i * 8);
    }
    cpa16(smb + 32768u + swz(brow, bq * 2),     gB);
    cpa16(smb + 32768u + swz(brow, bq * 2 + 1), gB + 8);
    CP_COMMIT();
    CP_WAIT0();
    __syncthreads();

    float acc[4][2][4] = {};
    cstage_w(smb, acc, mbase, nbase, lane);

    const float scale = 0.125f;
    #pragma unroll
    for (int i = 0; i < 4; i++) {
        #pragma unroll
        for (int j = 0; j < 2; j++) {
            int rr = row0 + mbase + i * 16 + (lane >> 2);
            int cc = col0 + nbase + j * 8 + (lane & 3) * 2;
            #pragma unroll
            for (int half = 0; half < 2; half++) {
                int r = rr + half * 8;
                float* orow = Wout + ((size_t)bh * Sn + r) * Sn;
                orow[cc]     = acc[i][j][half * 2 + 0] * scale + mask[bb * Sn + cc];
                orow[cc + 1] = acc[i][j][half * 2 + 1] * scale + mask[bb * Sn + cc + 1];
            }
        }
    }
}

// ---------------------------------------------------------------------------
// Kernel 3: row softmax; writes fp32 weights + single fp16 band [0, blockend).
// ---------------------------------------------------------------------------
__global__ __launch_bounds__(256) void softmax_kernel(float* __restrict__ Wm) {
    __shared__ float buf[Sn];
    __shared__ float red[8];
    int row = blockIdx.x;
    int q = row & (Sn - 1);
    int len = q + 1;
    int blockend = ((q >> 7) + 1) << 7;
    float* wrow = Wm + (size_t)row * Sn;
    size_t wb = (size_t)row * Sn;
    int tid = threadIdx.x;
    int lane = tid & 31, warp = tid >> 5;

    float mx = -1e30f;
    for (int c = tid * 4; c < blockend; c += 1024) {
        float4 v = *(const float4*)&wrow[c];
        *(float4*)&buf[c] = v;
        if (c + 3 < len) {
            mx = fmaxf(mx, fmaxf(fmaxf(v.x, v.y), fmaxf(v.z, v.w)));
        } else {
            if (c     < len) mx = fmaxf(mx, v.x);
            if (c + 1 < len) mx = fmaxf(mx, v.y);
            if (c + 2 < len) mx = fmaxf(mx, v.z);
            if (c + 3 < len) mx = fmaxf(mx, v.w);
        }
    }
    #pragma unroll
    for (int o = 16; o > 0; o >>= 1) mx = fmaxf(mx, __shfl_xor_sync(0xffffffffu, mx, o));
    if (lane == 0) red[warp] = mx;
    __syncthreads();
    if (tid < 32) {
        float t = (tid < 8) ? red[tid] : -1e30f;
        #pragma unroll
        for (int o = 4; o > 0; o >>= 1) t = fmaxf(t, __shfl_xor_sync(0xffffffffu, t, o));
        if (tid == 0) red[0] = t;
    }
    __syncthreads();
    mx = red[0];
    __syncthreads();

    float sum = 0.0f;
    for (int c = tid * 4; c < blockend; c += 1024) {
        float4 v = *(const float4*)&buf[c];
        float e0 = (c     < len) ? __expf(v.x - mx) : 0.0f;
        float e1 = (c + 1 < len) ? __expf(v.y - mx) : 0.0f;
        float e2 = (c + 2 < len) ? __expf(v.z - mx) : 0.0f;
        float e3 = (c + 3 < len) ? __expf(v.w - mx) : 0.0f;
        sum += (e0 + e1) + (e2 + e3);
        *(float4*)&buf[c] = make_float4(e0, e1, e2, e3);
    }
    #pragma unroll
    for (int o = 16; o > 0; o >>= 1) sum += __shfl_xor_sync(0xffffffffu, sum, o);
    if (lane == 0) red[warp] = sum;
    __syncthreads();
    if (tid < 32) {
        float t = (tid < 8) ? red[tid] : 0.0f;
        #pragma unroll
        for (int o = 4; o > 0; o >>= 1) t += __shfl_xor_sync(0xffffffffu, t, o);
        if (tid == 0) red[0] = t;
    }
    __syncthreads();
    float inv = 1.0f / red[0];

    for (int c = tid * 4; c < blockend; c += 1024) {
        float4 v = *(const float4*)&buf[c];
        v.x *= inv; v.y *= inv; v.z *= inv; v.w *= inv;
        *(float4*)&wrow[c] = v;
        *(uint2*)&g_w_h[wb + c] = make_uint2(pack2(v.x, v.y), pack2(v.z, v.w));
    }
    for (int c = blockend + tid * 4; c < Sn; c += 1024)
        *(float4*)&wrow[c] = make_float4(0.f, 0.f, 0.f, 0.f);
}

// ---------------------------------------------------------------------------
// Kernel 4: attn_heads = weights @ V. A = w single, B = v split. k64 stages.
// ---------------------------------------------------------------------------
__global__ __launch_bounds__(256, 2) void av_kernel() {
    extern __shared__ __align__(16) char dynsmem[];
    const uint32_t smb = s2u(dynsmem);
    int qb = gridDim.x - 1 - blockIdx.x;   // longest first
    int bh = blockIdx.y;
    int tid = threadIdx.x, lane = tid & 31, wid = tid >> 5;
    int row0 = qb * 128;
    int mbase = (wid & 1) * 64, nbase = (wid >> 1) * 16;
    int srow = tid >> 1, sh = tid & 1;
    int brow = tid >> 2, bq = tid & 3;
    const __half* gA  = g_w_h + (size_t)bh * Sn * Sn + (size_t)(row0 + srow) * Sn + sh * 32;
    const __half* gBh = g_v_h + ((size_t)bh * HDn + brow) * Sn + bq * 16;
    const __half* gBl = g_v_l + ((size_t)bh * HDn + brow) * Sn + bq * 16;
    uint32_t dA[4];
    #pragma unroll
    for (int i = 0; i < 4; i++) dA[i] = swz(srow, sh * 4 + i);
    uint32_t dB0 = swz(brow, bq * 2), dB1 = swz(brow, bq * 2 + 1);

    float acc[4][2][4] = {};
    const int T = (qb + 1) * 2;   // k64 stages over causal prefix

    #define AISSUE(t) do { uint32_t sb = smb + ((t) & 1) * SLOT_AV; \
        _Pragma("unroll") for (int i = 0; i < 4; i++) \
            cpa16(sb + dA[i], gA + (t) * 64 + i * 8); \
        cpa16(sb + 16384 + dB0, gBh + (t) * 64);  cpa16(sb + 16384 + dB1, gBh + (t) * 64 + 8); \
        cpa16(sb + 24576 + dB0, gBl + (t) * 64);  cpa16(sb + 24576 + dB1, gBl + (t) * 64 + 8); } while (0)

    AISSUE(0); CP_COMMIT();
    for (int t = 0; t < T; t++) {
        CP_WAIT0();
        __syncthreads();
        if (t + 1 < T) AISSUE(t + 1);
        CP_COMMIT();
        cstage_av(smb + (t & 1) * SLOT_AV, acc, mbase, nbase, lane);
    }
    #undef AISSUE

    #pragma unroll
    for (int i = 0; i < 4; i++) {
        #pragma unroll
        for (int j = 0; j < 2; j++) {
            int rr = row0 + mbase + i * 16 + (lane >> 2);
            int cc = nbase + j * 8 + (lane & 3) * 2;
            #pragma unroll
            for (int half = 0; half < 2; half++) {
                int r = rr + half * 8;
                uint32_t ph, pl;
                split2(acc[i][j][half * 2 + 0], acc[i][j][half * 2 + 1], ph, pl);
                size_t idx = ((size_t)bh * Sn + r) * HDn + cc;
                *(uint32_t*)&g_att_h[idx] = ph;
                *(uint32_t*)&g_att_l[idx] = pl;
            }
        }
    }
}

// ---------------------------------------------------------------------------
// Kernel 5: output projection. A = att split (head-transpose), B = wp single.
// ---------------------------------------------------------------------------
__global__ __launch_bounds__(256, 2) void proj_gemm(const float* __restrict__ bias,
                                                    float* __restrict__ out) {
    extern __shared__ __align__(16) char dynsmem[];
    const uint32_t smb = s2u(dynsmem);
    const int K = 1024, N = 1024;
    int tid = threadIdx.x, lane = tid & 31, wid = tid >> 5;
    int row0 = blockIdx.y * 128, col0 = blockIdx.x * 64;
    int mbase = (wid & 1) * 64, nbase = (wid >> 1) * 16;
    int srow = tid >> 1, sh = tid & 1;
    int brow = tid >> 2, bq = tid & 3;
    int arow = row0 + srow;
    int ab = arow >> 11, as = arow & 2047;
    size_t abase = (((size_t)ab * Hn) * Sn + as) * HDn + sh * 32;  // + head*Sn*HDn
    const __half* gB = s_wp_h + (size_t)(col0 + brow) * K + bq * 16;
    uint32_t dA[4];
    #pragma unroll
    for (int i = 0; i < 4; i++) dA[i] = swz(srow, sh * 4 + i);
    uint32_t dB0 = 32768u + swz(brow, bq * 2), dB1 = 32768u + swz(brow, bq * 2 + 1);

    float acc[4][2][4] = {};
    const int T = K / 64;   // 16 stages; stage t = head t

    #define PISSUE(t) do { uint32_t sb = smb + ((t) & 1) * SLOT_W; \
        size_t so = abase + (size_t)(t) * Sn * HDn; \
        _Pragma("unroll") for (int i = 0; i < 4; i++) { \
            cpa16(sb + dA[i],          g_att_h + so + i * 8); \
            cpa16(sb + 16384 + dA[i],  g_att_l + so + i * 8); } \
        cpa16(sb + dB0, gB + (t) * 64);  cpa16(sb + dB1, gB + (t) * 64 + 8); } while (0)

    PISSUE(0); CP_COMMIT();
    for (int t = 0; t < T; t++) {
        CP_WAIT0();
        __syncthreads();
        if (t + 1 < T) PISSUE(t + 1);
        CP_COMMIT();
        cstage_w(smb + (t & 1) * SLOT_W, acc, mbase, nbase, lane);
    }
    #undef PISSUE

    #pragma unroll
    for (int i = 0; i < 4; i++) {
        #pragma unroll
        for (int j = 0; j < 2; j++) {
            int rr = row0 + mbase + i * 16 + (lane >> 2);
            int cc = col0 + nbase + j * 8 + (lane & 3) * 2;
            #pragma unroll
            for (int half = 0; half < 2; half++) {
                int r = rr + half * 8;
                out[(size_t)r * N + cc]     = acc[i][j][half * 2 + 0] + bias[cc];
                out[(size_t)r * N + cc + 1] = acc[i][j][half * 2 + 1] + bias[cc + 1];
            }
        }
    }
}

// ---------------------------------------------------------------------------
extern "C" void kernel_launch(void* const* d_in, const int* in_sizes, int n_in,
                              void* d_out, int out_size) {
    (void)in_sizes; (void)n_in; (void)out_size;
    const float* hs     = (const float*)d_in[0];
    const float* mask   = (const float*)d_in[1];
    const float* w_attn = (const float*)d_in[2];
    const float* b_attn = (const float*)d_in[3];
    const float* w_proj = (const float*)d_in[4];
    const float* b_proj = (const float*)d_in[5];

    float* attn_out = (float*)d_out;                          // [B,S,D]
    float* weights  = (float*)d_out + (size_t)Bn * Sn * Dn;   // [B,H,S,S]

    cudaFuncSetAttribute(qkv_gemm,      cudaFuncAttributeMaxDynamicSharedMemorySize, SMEM_W);
    cudaFuncSetAttribute(scores_kernel, cudaFuncAttributeMaxDynamicSharedMemorySize, SMEM_SC);
    cudaFuncSetAttribute(av_kernel,     cudaFuncAttributeMaxDynamicSharedMemorySize, SMEM_AV);
    cudaFuncSetAttribute(proj_gemm,     cudaFuncAttributeMaxDynamicSharedMemorySize, SMEM_W);

    __half *wa_h, *wp_h;
    cudaGetSymbolAddress((void**)&wa_h, s_wa_h);
    cudaGetSymbolAddress((void**)&wp_h, s_wp_h);

    split_hs<<<BSn * Dn / 1024, 256>>>(hs);
    split_transpose<<<dim3(N3D / 32, Dn / 32), 256>>>(w_attn, wa_h, Dn, N3D);
    split_transpose<<<dim3(Dn / 32, Dn / 32), 256>>>(w_proj, wp_h, Dn, Dn);
    qkv_gemm<<<dim3(N3D / 64, BSn / 128), 256, SMEM_W>>>(b_attn);
    scores_kernel<<<dim3(272, Bn * Hn), 256, SMEM_SC>>>(mask, weights);
    softmax_kernel<<<dim3(Bn * Hn * Sn), 256>>>(weights);
    av_kernel<<<dim3(Sn / 128, Bn * Hn), 256, SMEM_AV>>>();
    proj_gemm<<<dim3(Dn / 64, BSn / 128), 256, SMEM_W>>>(b_proj, attn_out);
}

// round 11
// speedup vs baseline: 1.3181x; 1.1083x over previous
#include <cuda_runtime.h>
#include <cuda_fp16.h>
#include <math.h>
#include <stdint.h>

#define Bn 2
#define Sn 2048
#define Dn 1024
#define Hn 16
#define HDn 64
#define BSn (Bn*Sn)      // 4096
#define N3D (3*Dn)       // 3072
#define NQKV (Bn*Hn*Sn*HDn)

// wide stage (128m x 128n, k64): Ah 16KB | Al 16KB | B 16KB = 48KB
#define SLOT_W  49152
#define SMEM_W  (2*SLOT_W)    // 98304 -> 2 CTAs/SM
#define SMEM_SC SLOT_W        // scores single-shot K=64
// av stage (128m x 64n, k64): A 16KB | Bh 8KB | Bl 8KB = 32KB
#define SLOT_AV 32768
#define SMEM_AV (2*SLOT_AV)   // 65536 -> 3 CTAs/SM

// ---------------- fp16 scratch (device globals) ----------------
__device__ __half s_hs_h[BSn*Dn],  s_hs_l[BSn*Dn];   // hidden states split
__device__ __half s_wa_h[N3D*Dn];                    // w_attn^T single
__device__ __half s_wp_h[Dn*Dn];                     // w_proj^T single
__device__ __half g_q_h[NQKV], g_q_l[NQKV];          // q split   [bh][s][hd]
__device__ __half g_k_h[NQKV];                       // k single  [bh][s][hd]
__device__ __half g_v_h[NQKV], g_v_l[NQKV];          // v split   [bh][hd][s]
__device__ __half g_att_h[NQKV], g_att_l[NQKV];      // att split [bh][s][hd]
__device__ __half g_w_h[(size_t)Bn*Hn*Sn*Sn];        // weights single

// ---------------- helpers ----------------
__device__ __forceinline__ uint32_t s2u(const void* p) {
    return (uint32_t)__cvta_generic_to_shared(p);
}
__device__ __forceinline__ void ldsm4(uint32_t& r0, uint32_t& r1, uint32_t& r2,
                                      uint32_t& r3, uint32_t a) {
    asm volatile("ldmatrix.sync.aligned.m8n8.x4.shared.b16 {%0,%1,%2,%3},[%4];"
                 : "=r"(r0), "=r"(r1), "=r"(r2), "=r"(r3) : "r"(a));
}
#define MMAF(c, a, b) asm volatile( \
    "mma.sync.aligned.m16n8k16.row.col.f32.f16.f16.f32 " \
    "{%0,%1,%2,%3},{%4,%5,%6,%7},{%8,%9},{%0,%1,%2,%3};" \
    : "+f"((c)[0]), "+f"((c)[1]), "+f"((c)[2]), "+f"((c)[3]) \
    : "r"((a)[0]), "r"((a)[1]), "r"((a)[2]), "r"((a)[3]), "r"((b)[0]), "r"((b)[1]))

__device__ __forceinline__ void cpa16(uint32_t dst, const void* src) {
    asm volatile("cp.async.cg.shared.global [%0], [%1], 16;" :: "r"(dst), "l"(src));
}
#define CP_COMMIT() asm volatile("cp.async.commit_group;")
#define CP_WAIT0()  asm volatile("cp.async.wait_group 0;")

// byte offset of 16B chunk c (0..7) in swizzled 128B row
__device__ __forceinline__ uint32_t swz(int row, int c) {
    return (uint32_t)row * 128u + (uint32_t)((c ^ (row & 7)) << 4);
}

__device__ __forceinline__ void split2(float x, float y, uint32_t& ph, uint32_t& pl) {
    __half2 h2 = __floats2half2_rn(x, y);
    ph = *reinterpret_cast<uint32_t*>(&h2);
    __half2 l2 = __floats2half2_rn(x - __half2float(__low2half(h2)),
                                   y - __half2float(__high2half(h2)));
    pl = *reinterpret_cast<uint32_t*>(&l2);
}
__device__ __forceinline__ uint32_t pack2(float x, float y) {
    __half2 h2 = __floats2half2_rn(x, y);
    return *reinterpret_cast<uint32_t*>(&h2);
}

// wide stage (k64): split A (Ah @0, Al @16384), single B (@32768, 128 rows).
// warp grid 2m x 4n: warp tile 64m x 32n; acc[4][4][4].
__device__ __forceinline__ void cstage_w(uint32_t sb, float acc[4][4][4],
                                         int mbase, int nbase, int lane) {
    #pragma unroll
    for (int kk = 0; kk < 4; kk++) {
        uint32_t bf[4][2];
        #pragma unroll
        for (int jg = 0; jg < 2; jg++) {
            int brow = nbase + jg * 16 + (lane & 7) + ((lane >> 4) << 3);
            int bch = kk * 2 + ((lane >> 3) & 1);
            uint32_t r0, r1, r2, r3;
            ldsm4(r0, r1, r2, r3, sb + 32768u + swz(brow, bch));
            bf[jg * 2][0] = r0; bf[jg * 2][1] = r1;
            bf[jg * 2 + 1][0] = r2; bf[jg * 2 + 1][1] = r3;
        }
        #pragma unroll
        for (int i = 0; i < 4; i++) {
            int arow = mbase + i * 16 + (lane & 15);
            int ach = kk * 2 + (lane >> 4);
            uint32_t ah[4], al[4];
            ldsm4(ah[0], ah[1], ah[2], ah[3], sb + swz(arow, ach));
            ldsm4(al[0], al[1], al[2], al[3], sb + 16384u + swz(arow, ach));
            #pragma unroll
            for (int j = 0; j < 4; j++) {
                MMAF(acc[i][j], ah, bf[j]);
                MMAF(acc[i][j], al, bf[j]);
            }
        }
    }
}

// av stage (k64): single A (@0, 128 rows), split B (Bh @16384, Bl @24576, 64 rows).
// warp grid 4m x 2n: warp tile 32m x 32n; acc[2][4][4].
__device__ __forceinline__ void cstage_av(uint32_t sb, float acc[2][4][4],
                                          int mbase, int nbase, int lane) {
    #pragma unroll
    for (int kk = 0; kk < 4; kk++) {
        uint32_t bhf[4][2], blf[4][2];
        #pragma unroll
        for (int jg = 0; jg < 2; jg++) {
            int brow = nbase + jg * 16 + (lane & 7) + ((lane >> 4) << 3);
            int bch = kk * 2 + ((lane >> 3) & 1);
            uint32_t r0, r1, r2, r3;
            ldsm4(r0, r1, r2, r3, sb + 16384u + swz(brow, bch));
            bhf[jg * 2][0] = r0; bhf[jg * 2][1] = r1;
            bhf[jg * 2 + 1][0] = r2; bhf[jg * 2 + 1][1] = r3;
            ldsm4(r0, r1, r2, r3, sb + 24576u + swz(brow, bch));
            blf[jg * 2][0] = r0; blf[jg * 2][1] = r1;
            blf[jg * 2 + 1][0] = r2; blf[jg * 2 + 1][1] = r3;
        }
        #pragma unroll
        for (int i = 0; i < 2; i++) {
            int arow = mbase + i * 16 + (lane & 15);
            int ach = kk * 2 + (lane >> 4);
            uint32_t ah[4];
            ldsm4(ah[0], ah[1], ah[2], ah[3], sb + swz(arow, ach));
            #pragma unroll
            for (int j = 0; j < 4; j++) {
                MMAF(acc[i][j], ah, bhf[j]);
                MMAF(acc[i][j], ah, blf[j]);
            }
        }
    }
}

// ---------------------------------------------------------------------------
// Kernel 0a: split hidden states.
// ---------------------------------------------------------------------------
__global__ __launch_bounds__(256) void split_hs(const float* __restrict__ hs) {
    int i = (blockIdx.x * 256 + threadIdx.x) * 4;
    float4 v = *(const float4*)&hs[i];
    uint32_t ph0, pl0, ph1, pl1;
    split2(v.x, v.y, ph0, pl0);
    split2(v.z, v.w, ph1, pl1);
    *(uint2*)&s_hs_h[i] = make_uint2(ph0, ph1);
    *(uint2*)&s_hs_l[i] = make_uint2(pl0, pl1);
}

// ---------------------------------------------------------------------------
// Kernel 0b: tiled transpose of [K,N] weight -> single fp16 [N,K].
// ---------------------------------------------------------------------------
__global__ __launch_bounds__(256) void split_transpose(const float* __restrict__ in,
                                                       __half* __restrict__ oh,
                                                       int K, int N) {
    __shared__ float t[32][33];
    int nb = blockIdx.x * 32, kb = blockIdx.y * 32;
    int tx = threadIdx.x & 31, ty = threadIdx.x >> 5;
    #pragma unroll
    for (int i = 0; i < 4; i++) {
        int r = ty + i * 8;
        t[r][tx] = in[(size_t)(kb + r) * N + nb + tx];
    }
    __syncthreads();
    #pragma unroll
    for (int i = 0; i < 4; i++) {
        int r = ty + i * 8;
        oh[(size_t)(nb + r) * K + kb + tx] = __float2half_rn(t[tx][r]);
    }
}

// ---------------------------------------------------------------------------
// Kernel 1: QKV projection. block 128m x 128n, warp 64x32, k64 x 16 stages.
// ---------------------------------------------------------------------------
__global__ __launch_bounds__(256, 2) void qkv_gemm(const float* __restrict__ bias) {
    extern __shared__ __align__(16) char dynsmem[];
    const uint32_t smb = s2u(dynsmem);
    const int K = 1024;
    int tid = threadIdx.x, lane = tid & 31, wid = tid >> 5;
    int row0 = blockIdx.y * 128, col0 = blockIdx.x * 128;
    int mbase = (wid & 1) * 64, nbase = (wid >> 1) * 32;
    int srow = tid >> 1, sh = tid & 1;          // loaders: 2 threads/row, 64B half
    const __half* gAh = s_hs_h + (size_t)(row0 + srow) * K + sh * 32;
    const __half* gAl = s_hs_l + (size_t)(row0 + srow) * K + sh * 32;
    const __half* gB  = s_wa_h + (size_t)(col0 + srow) * K + sh * 32;
    uint32_t dA[4];
    #pragma unroll
    for (int i = 0; i < 4; i++) dA[i] = swz(srow, sh * 4 + i);

    float acc[4][4][4] = {};
    const int T = K / 64;   // 16 stages

    #define QISSUE(t) do { uint32_t sb = smb + ((t) & 1) * SLOT_W; \
        _Pragma("unroll") for (int i = 0; i < 4; i++) { \
            cpa16(sb + dA[i],          gAh + (t) * 64 + i * 8); \
            cpa16(sb + 16384 + dA[i],  gAl + (t) * 64 + i * 8); \
            cpa16(sb + 32768 + dA[i],  gB  + (t) * 64 + i * 8); } } while (0)

    QISSUE(0); CP_COMMIT();
    for (int t = 0; t < T; t++) {
        CP_WAIT0();
        __syncthreads();
        if (t + 1 < T) QISSUE(t + 1);
        CP_COMMIT();
        cstage_w(smb + (t & 1) * SLOT_W, acc, mbase, nbase, lane);
    }
    #undef QISSUE

    #pragma unroll
    for (int i = 0; i < 4; i++) {
        #pragma unroll
        for (int j = 0; j < 4; j++) {
            int rr = row0 + mbase + i * 16 + (lane >> 2);
            int cc = col0 + nbase + j * 8 + (lane & 3) * 2;
            #pragma unroll
            for (int half = 0; half < 2; half++) {
                int r = rr + half * 8;
                int b = r >> 11, s = r & 2047;
                float v0 = acc[i][j][half * 2 + 0] + bias[cc];
                float v1 = acc[i][j][half * 2 + 1] + bias[cc + 1];
                int which = cc >> 10;
                int dcol = cc & 1023;
                int h = dcol >> 6, hd = dcol & 63;
                int bh = b * Hn + h;
                if (which == 0) {          // q: split
                    uint32_t ph, pl; split2(v0, v1, ph, pl);
                    size_t idx = ((size_t)bh * Sn + s) * HDn + hd;
                    *(uint32_t*)&g_q_h[idx] = ph; *(uint32_t*)&g_q_l[idx] = pl;
                } else if (which == 1) {   // k: single
                    size_t idx = ((size_t)bh * Sn + s) * HDn + hd;
                    *(uint32_t*)&g_k_h[idx] = pack2(v0, v1);
                } else {                   // v: split, transposed [bh][hd][s]
                    uint32_t ph, pl; split2(v0, v1, ph, pl);
                    size_t i0 = ((size_t)bh * HDn + hd) * Sn + s;
                    size_t i1 = ((size_t)bh * HDn + hd + 1) * Sn + s;
                    ((uint16_t*)g_v_h)[i0] = (uint16_t)(ph & 0xffff);
                    ((uint16_t*)g_v_h)[i1] = (uint16_t)(ph >> 16);
                    ((uint16_t*)g_v_l)[i0] = (uint16_t)(pl & 0xffff);
                    ((uint16_t*)g_v_l)[i1] = (uint16_t)(pl >> 16);
                }
            }
        }
    }
}

// ---------------------------------------------------------------------------
// Kernel 2: raw scores, lower-tri 128q x 128k tiles, K=64 single-shot.
// A = q split, B = k single. grid.x = 136 (cum qb*(qb+1)/2).
// ---------------------------------------------------------------------------
__global__ __launch_bounds__(256, 2) void scores_kernel(const float* __restrict__ mask,
                                                        float* __restrict__ Wout) {
    extern __shared__ __align__(16) char dynsmem[];
    const uint32_t smb = s2u(dynsmem);
    int idx = blockIdx.x;
    int qb = (int)((sqrtf(8.0f * idx + 1.0f) - 1.0f) * 0.5f);
    while ((qb + 1) * (qb + 2) / 2 <= idx) qb++;
    while (qb * (qb + 1) / 2 > idx) qb--;
    int kb = idx - qb * (qb + 1) / 2;
    int bh = blockIdx.y;
    int bb = bh >> 4;
    int tid = threadIdx.x, lane = tid & 31, wid = tid >> 5;
    int row0 = qb * 128, col0 = kb * 128;
    int mbase = (wid & 1) * 64, nbase = (wid >> 1) * 32;
    int srow = tid >> 1, sh = tid & 1;
    const __half* gAh = g_q_h + ((size_t)bh * Sn + row0 + srow) * HDn + sh * 32;
    const __half* gAl = g_q_l + ((size_t)bh * Sn + row0 + srow) * HDn + sh * 32;
    const __half* gB  = g_k_h + ((size_t)bh * Sn + col0 + srow) * HDn + sh * 32;

    #pragma unroll
    for (int i = 0; i < 4; i++) {
        uint32_t d = swz(srow, sh * 4 + i);
        cpa16(smb + d,          gAh + i * 8);
        cpa16(smb + 16384 + d,  gAl + i * 8);
        cpa16(smb + 32768 + d,  gB  + i * 8);
    }
    CP_COMMIT();
    CP_WAIT0();
    __syncthreads();

    float acc[4][4][4] = {};
    cstage_w(smb, acc, mbase, nbase, lane);

    const float scale = 0.125f;
    #pragma unroll
    for (int i = 0; i < 4; i++) {
        #pragma unroll
        for (int j = 0; j < 4; j++) {
            int rr = row0 + mbase + i * 16 + (lane >> 2);
            int cc = col0 + nbase + j * 8 + (lane & 3) * 2;
            #pragma unroll
            for (int half = 0; half < 2; half++) {
                int r = rr + half * 8;
                float* orow = Wout + ((size_t)bh * Sn + r) * Sn;
                orow[cc]     = acc[i][j][half * 2 + 0] * scale + mask[bb * Sn + cc];
                orow[cc + 1] = acc[i][j][half * 2 + 1] * scale + mask[bb * Sn + cc + 1];
            }
        }
    }
}

// ---------------------------------------------------------------------------
// Kernel 3: row softmax; fp32 weights (output) + fp16 single band.
// ---------------------------------------------------------------------------
__global__ __launch_bounds__(256) void softmax_kernel(float* __restrict__ Wm) {
    __shared__ float buf[Sn];
    __shared__ float red[8];
    int row = blockIdx.x;
    int q = row & (Sn - 1);
    int len = q + 1;
    int blockend = ((q >> 7) + 1) << 7;
    float* wrow = Wm + (size_t)row * Sn;
    size_t wb = (size_t)row * Sn;
    int tid = threadIdx.x;
    int lane = tid & 31, warp = tid >> 5;

    float mx = -1e30f;
    for (int c = tid * 4; c < blockend; c += 1024) {
        float4 v = *(const float4*)&wrow[c];
        *(float4*)&buf[c] = v;
        if (c + 3 < len) {
            mx = fmaxf(mx, fmaxf(fmaxf(v.x, v.y), fmaxf(v.z, v.w)));
        } else {
            if (c     < len) mx = fmaxf(mx, v.x);
            if (c + 1 < len) mx = fmaxf(mx, v.y);
            if (c + 2 < len) mx = fmaxf(mx, v.z);
            if (c + 3 < len) mx = fmaxf(mx, v.w);
        }
    }
    #pragma unroll
    for (int o = 16; o > 0; o >>= 1) mx = fmaxf(mx, __shfl_xor_sync(0xffffffffu, mx, o));
    if (lane == 0) red[warp] = mx;
    __syncthreads();
    if (tid < 32) {
        float t = (tid < 8) ? red[tid] : -1e30f;
        #pragma unroll
        for (int o = 4; o > 0; o >>= 1) t = fmaxf(t, __shfl_xor_sync(0xffffffffu, t, o));
        if (tid == 0) red[0] = t;
    }
    __syncthreads();
    mx = red[0];
    __syncthreads();

    float sum = 0.0f;
    for (int c = tid * 4; c < blockend; c += 1024) {
        float4 v = *(const float4*)&buf[c];
        float e0 = (c     < len) ? __expf(v.x - mx) : 0.0f;
        float e1 = (c + 1 < len) ? __expf(v.y - mx) : 0.0f;
        float e2 = (c + 2 < len) ? __expf(v.z - mx) : 0.0f;
        float e3 = (c + 3 < len) ? __expf(v.w - mx) : 0.0f;
        sum += (e0 + e1) + (e2 + e3);
        *(float4*)&buf[c] = make_float4(e0, e1, e2, e3);
    }
    #pragma unroll
    for (int o = 16; o > 0; o >>= 1) sum += __shfl_xor_sync(0xffffffffu, sum, o);
    if (lane == 0) red[warp] = sum;
    __syncthreads();
    if (tid < 32) {
        float t = (tid < 8) ? red[tid] : 0.0f;
        #pragma unroll
        for (int o = 4; o > 0; o >>= 1) t += __shfl_xor_sync(0xffffffffu, t, o);
        if (tid == 0) red[0] = t;
    }
    __syncthreads();
    float inv = 1.0f / red[0];

    for (int c = tid * 4; c < blockend; c += 1024) {
        float4 v = *(const float4*)&buf[c];
        v.x *= inv; v.y *= inv; v.z *= inv; v.w *= inv;
        *(float4*)&wrow[c] = v;
        *(uint2*)&g_w_h[wb + c] = make_uint2(pack2(v.x, v.y), pack2(v.z, v.w));
    }
    for (int c = blockend + tid * 4; c < Sn; c += 1024)
        *(float4*)&wrow[c] = make_float4(0.f, 0.f, 0.f, 0.f);
}

// ---------------------------------------------------------------------------
// Kernel 4: attn_heads = weights @ V. block 128m x 64n, warp 32x32, k64 stages.
// A = w single, B = v split.
// ---------------------------------------------------------------------------
__global__ __launch_bounds__(256, 3) void av_kernel() {
    extern __shared__ __align__(16) char dynsmem[];
    const uint32_t smb = s2u(dynsmem);
    int qb = gridDim.x - 1 - blockIdx.x;   // longest first
    int bh = blockIdx.y;
    int tid = threadIdx.x, lane = tid & 31, wid = tid >> 5;
    int row0 = qb * 128;
    int mbase = (wid & 3) * 32, nbase = (wid >> 2) * 32;
    int srow = tid >> 1, sh = tid & 1;
    int brow = tid >> 2, bq = tid & 3;
    const __half* gA  = g_w_h + (size_t)bh * Sn * Sn + (size_t)(row0 + srow) * Sn + sh * 32;
    const __half* gBh = g_v_h + ((size_t)bh * HDn + brow) * Sn + bq * 16;
    const __half* gBl = g_v_l + ((size_t)bh * HDn + brow) * Sn + bq * 16;
    uint32_t dA[4];
    #pragma unroll
    for (int i = 0; i < 4; i++) dA[i] = swz(srow, sh * 4 + i);
    uint32_t dB0 = swz(brow, bq * 2), dB1 = swz(brow, bq * 2 + 1);

    float acc[2][4][4] = {};
    const int T = (qb + 1) * 2;

    #define AISSUE(t) do { uint32_t sb = smb + ((t) & 1) * SLOT_AV; \
        _Pragma("unroll") for (int i = 0; i < 4; i++) \
            cpa16(sb + dA[i], gA + (t) * 64 + i * 8); \
        cpa16(sb + 16384 + dB0, gBh + (t) * 64);  cpa16(sb + 16384 + dB1, gBh + (t) * 64 + 8); \
        cpa16(sb + 24576 + dB0, gBl + (t) * 64);  cpa16(sb + 24576 + dB1, gBl + (t) * 64 + 8); } while (0)

    AISSUE(0); CP_COMMIT();
    for (int t = 0; t < T; t++) {
        CP_WAIT0();
        __syncthreads();
        if (t + 1 < T) AISSUE(t + 1);
        CP_COMMIT();
        cstage_av(smb + (t & 1) * SLOT_AV, acc, mbase, nbase, lane);
    }
    #undef AISSUE

    #pragma unroll
    for (int i = 0; i < 2; i++) {
        #pragma unroll
        for (int j = 0; j < 4; j++) {
            int rr = row0 + mbase + i * 16 + (lane >> 2);
            int cc = nbase + j * 8 + (lane & 3) * 2;
            #pragma unroll
            for (int half = 0; half < 2; half++) {
                int r = rr + half * 8;
                uint32_t ph, pl;
                split2(acc[i][j][half * 2 + 0], acc[i][j][half * 2 + 1], ph, pl);
                size_t idx = ((size_t)bh * Sn + r) * HDn + cc;
                *(uint32_t*)&g_att_h[idx] = ph;
                *(uint32_t*)&g_att_l[idx] = pl;
            }
        }
    }
}

// ---------------------------------------------------------------------------
// Kernel 5: output projection. block 128m x 128n, warp 64x32, k64 stages.
// A = att split (head-transpose), B = wp single.
// ---------------------------------------------------------------------------
__global__ __launch_bounds__(256, 2) void proj_gemm(const float* __restrict__ bias,
                                                    float* __restrict__ out) {
    extern __shared__ __align__(16) char dynsmem[];
    const uint32_t smb = s2u(dynsmem);
    const int K = 1024, N = 1024;
    int tid = threadIdx.x, lane = tid & 31, wid = tid >> 5;
    int row0 = blockIdx.y * 128, col0 = blockIdx.x * 128;
    int mbase = (wid & 1) * 64, nbase = (wid >> 1) * 32;
    int srow = tid >> 1, sh = tid & 1;
    int arow = row0 + srow;
    int ab = arow >> 11, as = arow & 2047;
    size_t abase = (((size_t)ab * Hn) * Sn + as) * HDn + sh * 32;  // + head*Sn*HDn
    const __half* gB = s_wp_h + (size_t)(col0 + srow) * K + sh * 32;
    uint32_t dA[4];
    #pragma unroll
    for (int i = 0; i < 4; i++) dA[i] = swz(srow, sh * 4 + i);

    float acc[4][4][4] = {};
    const int T = K / 64;   // 16 stages; stage t = head t

    #define PISSUE(t) do { uint32_t sb = smb + ((t) & 1) * SLOT_W; \
        size_t so = abase + (size_t)(t) * Sn * HDn; \
        _Pragma("unroll") for (int i = 0; i < 4; i++) { \
            cpa16(sb + dA[i],          g_att_h + so + i * 8); \
            cpa16(sb + 16384 + dA[i],  g_att_l + so + i * 8); \
            cpa16(sb + 32768 + dA[i],  gB + (t) * 64 + i * 8); } } while (0)

    PISSUE(0); CP_COMMIT();
    for (int t = 0; t < T; t++) {
        CP_WAIT0();
        __syncthreads();
        if (t + 1 < T) PISSUE(t + 1);
        CP_COMMIT();
        cstage_w(smb + (t & 1) * SLOT_W, acc, mbase, nbase, lane);
    }
    #undef PISSUE

    #pragma unroll
    for (int i = 0; i < 4; i++) {
        #pragma unroll
        for (int j = 0; j < 4; j++) {
            int rr = row0 + mbase + i * 16 + (lane >> 2);
            int cc = col0 + nbase + j * 8 + (lane & 3) * 2;
            #pragma unroll
            for (int half = 0; half < 2; half++) {
                int r = rr + half * 8;
                out[(size_t)r * N + cc]     = acc[i][j][half * 2 + 0] + bias[cc];
                out[(size_t)r * N + cc + 1] = acc[i][j][half * 2 + 1] + bias[cc + 1];
            }
        }
    }
}

// ---------------------------------------------------------------------------
extern "C" void kernel_launch(void* const* d_in, const int* in_sizes, int n_in,
                              void* d_out, int out_size) {
    (void)in_sizes; (void)n_in; (void)out_size;
    const float* hs     = (const float*)d_in[0];
    const float* mask   = (const float*)d_in[1];
    const float* w_attn = (const float*)d_in[2];
    const float* b_attn = (const float*)d_in[3];
    const float* w_proj = (const float*)d_in[4];
    const float* b_proj = (const float*)d_in[5];

    float* attn_out = (float*)d_out;                          // [B,S,D]
    float* weights  = (float*)d_out + (size_t)Bn * Sn * Dn;   // [B,H,S,S]

    cudaFuncSetAttribute(qkv_gemm,      cudaFuncAttributeMaxDynamicSharedMemorySize, SMEM_W);
    cudaFuncSetAttribute(scores_kernel, cudaFuncAttributeMaxDynamicSharedMemorySize, SMEM_SC);
    cudaFuncSetAttribute(av_kernel,     cudaFuncAttributeMaxDynamicSharedMemorySize, SMEM_AV);
    cudaFuncSetAttribute(proj_gemm,     cudaFuncAttributeMaxDynamicSharedMemorySize, SMEM_W);

    __half *wa_h, *wp_h;
    cudaGetSymbolAddress((void**)&wa_h, s_wa_h);
    cudaGetSymbolAddress((void**)&wp_h, s_wp_h);

    split_hs<<<BSn * Dn / 1024, 256>>>(hs);
    split_transpose<<<dim3(N3D / 32, Dn / 32), 256>>>(w_attn, wa_h, Dn, N3D);
    split_transpose<<<dim3(Dn / 32, Dn / 32), 256>>>(w_proj, wp_h, Dn, Dn);
    qkv_gemm<<<dim3(N3D / 128, BSn / 128), 256, SMEM_W>>>(b_attn);
    scores_kernel<<<dim3(136, Bn * Hn), 256, SMEM_SC>>>(mask, weights);
    softmax_kernel<<<dim3(Bn * Hn * Sn), 256>>>(weights);
    av_kernel<<<dim3(Sn / 128, Bn * Hn), 256, SMEM_AV>>>();
    proj_gemm<<<dim3(Dn / 128, BSn / 128), 256, SMEM_W>>>(b_proj, attn_out);
}